// round 15
// baseline (speedup 1.0000x reference)
#include <cuda_runtime.h>
#include <cstdint>

// CostVolumn: out[b, dy*9+dx, y, x] = leaky( mean_c( c1[b,c,y,x] * warped_pad[b,c,y+dy-4, x+dx-4] ) )
// 8-wide x-tiles (1.33 B/MAC LDS), f32x2 load-native pairing, 3-stage cp.async ring, 2 CTAs/SM.

namespace {
constexpr int B_ = 8;
constexpr int C_ = 192;
constexpr int H_ = 128;
constexpr int W_ = 160;
constexpr int SR = 4;
constexpr int MO = 9;
constexpr int TH = 8;
constexpr int TW = 32;
constexpr int CC = 4;                   // channels per stage (keeps smem small)
constexpr int NCH = C_ / CC;            // 48
constexpr int HALO_H = TH + 2 * SR;     // 16
constexpr int HALO_W = TW + 2 * SR;     // 40
constexpr int NTHREADS = 4 * 8 * 9;     // 288
constexpr int HW = H_ * W_;

constexpr int SWROW = 44;   // w row stride; 44 mod 32 = 12 -> conflict-free phases
constexpr int SAROW = 36;   // a row stride; 36 mod 32 = 4  -> conflict-free

constexpr int SW_ELEMS = CC * HALO_H * SWROW;   // 2816 floats
constexpr int SA_ELEMS = CC * TH * SAROW;       // 1152 floats
constexpr int STAGE = SW_ELEMS + SA_ELEMS;      // 3968 floats
constexpr int NSTAGES = 3;
constexpr int SMEM_BYTES = NSTAGES * STAGE * 4; // 47616 B (x2 CTAs = 95.2 KB/SM)

// 16B staging units
constexpr int UW = CC * HALO_H * (HALO_W / 4);  // 640
constexpr int UC = CC * TH * (TW / 4);          // 256
constexpr int UTOT = UW + UC;                   // 896
constexpr int SLOTS = (UTOT + NTHREADS - 1) / NTHREADS;  // 4
}

using ull = unsigned long long;

__device__ __forceinline__ void fma2(ull& d, ull a, ull b) {
    asm("fma.rn.f32x2 %0, %1, %2, %0;" : "+l"(d) : "l"(a), "l"(b));
}
__device__ __forceinline__ void upk(ull v, float& lo, float& hi) {
    asm("mov.b64 {%0, %1}, %2;" : "=f"(lo), "=f"(hi) : "l"(v));  // register aliasing (free)
}
// (hi of p, lo of q) — one real 64-bit repack (2 MOVs)
__device__ __forceinline__ ull mkodd(ull p, ull q) {
    ull r;
    asm("{\n\t"
        ".reg .b32 plo, phi, qlo, qhi;\n\t"
        "mov.b64 {plo, phi}, %1;\n\t"
        "mov.b64 {qlo, qhi}, %2;\n\t"
        "mov.b64 %0, {phi, qlo};\n\t"
        "}"
        : "=l"(r) : "l"(p), "l"(q));
    return r;
}

__global__ __launch_bounds__(NTHREADS, 2)
void costvol_kernel(const float* __restrict__ c1,
                    const float* __restrict__ warped,
                    const float* __restrict__ alpha,
                    float* __restrict__ out) {
    extern __shared__ float smem[];

    const int q  = threadIdx.x;   // x-oct 0..3 (x = 8q..8q+7)
    const int ly = threadIdx.y;   // tile row 0..7
    const int dz = threadIdx.z;   // dy 0..8 (one warp per dz)
    const int tid = q + 4 * (ly + 8 * dz);

    const int x0 = blockIdx.x * TW;
    const int y0 = blockIdx.y * TH;
    const int b  = blockIdx.z;

    const float* __restrict__ c1b = c1 + (size_t)b * C_ * HW;
    const float* __restrict__ wb  = warped + (size_t)b * C_ * HW;

    // ---- staging slots as advancing global pointers ----
    const float* gp[SLOTS];
    uint32_t soff[SLOTS];
#pragma unroll
    for (int s = 0; s < SLOTS; s++) {
        gp[s] = nullptr; soff[s] = 0;
        int i = tid + NTHREADS * s;
        if (i < UW) {
            int cc = i / (HALO_H * 10);
            int rem = i % (HALO_H * 10);
            int hy = rem / 10;
            int seg = rem % 10;
            int gy = y0 + hy - SR;
            int gx = x0 - SR + seg * 4;
            soff[s] = (uint32_t)(cc * (HALO_H * SWROW) + hy * SWROW + seg * 4) * 4u;
            if (gy >= 0 && gy < H_ && gx >= 0 && gx + 4 <= W_)
                gp[s] = wb + cc * HW + gy * W_ + gx;
        } else if (i < UTOT) {
            int j = i - UW;
            int cc = j / (TH * 8);
            int rem = j % (TH * 8);
            int yy = rem / 8;
            int seg = rem % 8;
            soff[s] = (uint32_t)(SW_ELEMS + cc * (TH * SAROW) + yy * SAROW + seg * 4) * 4u;
            gp[s] = c1b + cc * HW + (y0 + yy) * W_ + (x0 + seg * 4);
        }
    }

    // ---- zero warped regions once in all stages (OOB halo padding persists) ----
    for (int st = 0; st < NSTAGES; st++)
        for (int i = tid; i < SW_ELEMS; i += NTHREADS)
            smem[st * STAGE + i] = 0.f;
    __syncthreads();

    const uint32_t smem_u32 = (uint32_t)__cvta_generic_to_shared(smem);

    auto issue_stage = [&](int kmod) {
        const uint32_t sbase = smem_u32 + (uint32_t)(kmod * STAGE) * 4u;
#pragma unroll
        for (int s = 0; s < SLOTS; s++) {
            if (gp[s]) {
                uint32_t sa = sbase + soff[s];
                asm volatile("cp.async.cg.shared.global [%0], [%1], 16;"
                             :: "r"(sa), "l"(gp[s]) : "memory");
                gp[s] += CC * HW;
            }
        }
        asm volatile("cp.async.commit_group;" ::: "memory");
    };

    issue_stage(0);
    issue_stage(1);
    issue_stage(2);

    // accumulators (8-wide):
    //  even dx=2d: accE[d][m], m: x-pairs (0,1)(2,3)(4,5)(6,7)
    //  odd  dx=2o+1: x0 scalar, pairs (1,2)(3,4)(5,6) in accO[o][m], x7 scalar
    ull accE[5][4], accO[4][3];
    float acc0[4], acc7[4];
#pragma unroll
    for (int d = 0; d < 5; d++)
#pragma unroll
        for (int m = 0; m < 4; m++) accE[d][m] = 0ull;
#pragma unroll
    for (int o = 0; o < 4; o++) {
#pragma unroll
        for (int m = 0; m < 3; m++) accO[o][m] = 0ull;
        acc0[o] = 0.f; acc7[o] = 0.f;
    }

    // fixed per-thread smem offsets
    const float* a_base = smem + SW_ELEMS + ly * SAROW + 8 * q;
    const float* w_base = smem + (ly + dz) * SWROW + 8 * q;

    int kmod = 0;          // k % 3, maintained by rotation
    for (int k = 0; k < NCH; k++) {
        if (k == 0) {
            asm volatile("cp.async.wait_group 2;" ::: "memory");
        } else if (k + 1 < NCH) {
            asm volatile("cp.async.wait_group 1;" ::: "memory");
        } else {
            asm volatile("cp.async.wait_group 0;" ::: "memory");
        }
        __syncthreads();   // stage k visible; all threads done with chunk k-1

        // buffer (k-1)%3 == (k+2)%3 now free -> refill
        int knext = kmod;  // (k+2)%3 == (k-1)%3
        if (k >= 1 && k + 2 < NCH) {
            knext = kmod - 1; if (knext < 0) knext += NSTAGES;
            issue_stage(knext);
        }

        const float* as = a_base + kmod * STAGE;
        const float* ws = w_base + kmod * STAGE;

#pragma unroll
        for (int cc = 0; cc < CC; cc++) {
            // a: 8 floats -> 4 even pairs straight from 2x LDS.128
            ulonglong2 ua0 = *reinterpret_cast<const ulonglong2*>(as + cc * (TH * SAROW));
            ulonglong2 ua1 = *reinterpret_cast<const ulonglong2*>(as + cc * (TH * SAROW) + 4);
            ull Ae[4] = {ua0.x, ua0.y, ua1.x, ua1.y};
            float a0, a1x, a6x, a7;
            upk(Ae[0], a0, a1x);
            upk(Ae[3], a6x, a7);
            // odd-shifted a pairs (a1,a2)(a3,a4)(a5,a6)
            ull Ao[3] = {mkodd(Ae[0], Ae[1]), mkodd(Ae[1], Ae[2]), mkodd(Ae[2], Ae[3])};

            // w: 16 floats -> 8 even pairs straight from 4x LDS.128
            const float* wrow = ws + cc * (HALO_H * SWROW);
            ulonglong2 u0 = *reinterpret_cast<const ulonglong2*>(wrow);
            ulonglong2 u1 = *reinterpret_cast<const ulonglong2*>(wrow + 4);
            ulonglong2 u2 = *reinterpret_cast<const ulonglong2*>(wrow + 8);
            ulonglong2 u3 = *reinterpret_cast<const ulonglong2*>(wrow + 12);
            ull P[8] = {u0.x, u0.y, u1.x, u1.y, u2.x, u2.y, u3.x, u3.y};

            // even dx = 2d: (a2m,a2m+1)*(w2d+2m, w2d+2m+1)
#pragma unroll
            for (int d = 0; d < 5; d++)
#pragma unroll
                for (int m = 0; m < 4; m++)
                    fma2(accE[d][m], Ae[m], P[d + m]);

            // odd dx = 2o+1
#pragma unroll
            for (int o = 0; o < 4; o++) {
                float wlo, whi;
                upk(P[o], wlo, whi);              // whi = w[2o+1] = w[dx]
                acc0[o] = fmaf(a0, whi, acc0[o]); // x0
#pragma unroll
                for (int m = 0; m < 3; m++)
                    fma2(accO[o][m], Ao[m], P[o + 1 + m]);
                upk(P[o + 4], wlo, whi);          // wlo = w[2o+8] = w[dx+7]
                acc7[o] = fmaf(a7, wlo, acc7[o]); // x7
            }
        }

        kmod++; if (kmod == NSTAGES) kmod = 0;
    }

    // ---- epilogue: mean + leaky, 2x float4 stores per dx ----
    const float al = __ldg(alpha);
    const float inv = 1.0f / (float)C_;
    const int gy = y0 + ly;
    const int gxbase = x0 + q * 8;

    auto emit = [&](int dx, const float* v8) {
        int o = dz * MO + dx;
        float* dst = out + ((size_t)(b * 81 + o) * H_ + gy) * W_ + gxbase;
        float4 v;
        float t;
        t = v8[0] * inv; v.x = (t >= 0.f) ? t : al * t;
        t = v8[1] * inv; v.y = (t >= 0.f) ? t : al * t;
        t = v8[2] * inv; v.z = (t >= 0.f) ? t : al * t;
        t = v8[3] * inv; v.w = (t >= 0.f) ? t : al * t;
        *reinterpret_cast<float4*>(dst) = v;
        t = v8[4] * inv; v.x = (t >= 0.f) ? t : al * t;
        t = v8[5] * inv; v.y = (t >= 0.f) ? t : al * t;
        t = v8[6] * inv; v.z = (t >= 0.f) ? t : al * t;
        t = v8[7] * inv; v.w = (t >= 0.f) ? t : al * t;
        *reinterpret_cast<float4*>(dst + 4) = v;
    };

#pragma unroll
    for (int d = 0; d < 5; d++) {
        float v8[8];
        upk(accE[d][0], v8[0], v8[1]);
        upk(accE[d][1], v8[2], v8[3]);
        upk(accE[d][2], v8[4], v8[5]);
        upk(accE[d][3], v8[6], v8[7]);
        emit(2 * d, v8);
    }
#pragma unroll
    for (int o = 0; o < 4; o++) {
        float v8[8];
        v8[0] = acc0[o];
        upk(accO[o][0], v8[1], v8[2]);
        upk(accO[o][1], v8[3], v8[4]);
        upk(accO[o][2], v8[5], v8[6]);
        v8[7] = acc7[o];
        emit(2 * o + 1, v8);
    }
}

extern "C" void kernel_launch(void* const* d_in, const int* in_sizes, int n_in,
                              void* d_out, int out_size) {
    const float* c1     = (const float*)d_in[0];
    const float* warped = (const float*)d_in[1];
    const float* alpha  = (const float*)d_in[2];
    float* out = (float*)d_out;

    cudaFuncSetAttribute(costvol_kernel,
                         cudaFuncAttributeMaxDynamicSharedMemorySize, SMEM_BYTES);

    dim3 block(4, 8, 9);              // 288 threads, 2 CTAs/SM
    dim3 grid(W_ / TW, H_ / TH, B_);  // (5, 16, 8) = 640 blocks
    costvol_kernel<<<grid, block, SMEM_BYTES>>>(c1, warped, alpha, out);
}

// round 17
// speedup vs baseline: 1.0516x; 1.0516x over previous
#include <cuda_runtime.h>
#include <cstdint>

// CostVolumn: out[b, dy*9+dx, y, x] = leaky( mean_c( c1[b,c,y,x] * warped_pad[b,c,y+dy-4, x+dx-4] ) )
// 8-wide x-tiles, CC=8 (24 chunks / 24 barriers), f32x2 load-native pairing,
// 3-stage cp.async ring (1 barrier/chunk), 2 CTAs/SM (190 KB smem/SM).

namespace {
constexpr int B_ = 8;
constexpr int C_ = 192;
constexpr int H_ = 128;
constexpr int W_ = 160;
constexpr int SR = 4;
constexpr int MO = 9;
constexpr int TH = 8;
constexpr int TW = 32;
constexpr int CC = 8;                   // channels per stage (24 chunks total)
constexpr int NCH = C_ / CC;            // 24
constexpr int HALO_H = TH + 2 * SR;     // 16
constexpr int HALO_W = TW + 2 * SR;     // 40
constexpr int NTHREADS = 4 * 8 * 9;     // 288
constexpr int HW = H_ * W_;

constexpr int SWROW = 44;   // w row stride; conflict-free phases
constexpr int SAROW = 36;   // a row stride; conflict-free

constexpr int SW_ELEMS = CC * HALO_H * SWROW;   // 5632 floats
constexpr int SA_ELEMS = CC * TH * SAROW;       // 2304 floats
constexpr int STAGE = SW_ELEMS + SA_ELEMS;      // 7936 floats
constexpr int NSTAGES = 3;
constexpr int SMEM_BYTES = NSTAGES * STAGE * 4; // 95232 B (x2 CTAs = 190.4 KB/SM)

// 16B staging units
constexpr int UW = CC * HALO_H * (HALO_W / 4);  // 1280
constexpr int UC = CC * TH * (TW / 4);          // 512
constexpr int UTOT = UW + UC;                   // 1792
constexpr int SLOTS = (UTOT + NTHREADS - 1) / NTHREADS;  // 7
}

using ull = unsigned long long;

__device__ __forceinline__ void fma2(ull& d, ull a, ull b) {
    asm("fma.rn.f32x2 %0, %1, %2, %0;" : "+l"(d) : "l"(a), "l"(b));
}
__device__ __forceinline__ void upk(ull v, float& lo, float& hi) {
    asm("mov.b64 {%0, %1}, %2;" : "=f"(lo), "=f"(hi) : "l"(v));  // register aliasing (free)
}
// (hi of p, lo of q) — one real 64-bit repack
__device__ __forceinline__ ull mkodd(ull p, ull q) {
    ull r;
    asm("{\n\t"
        ".reg .b32 plo, phi, qlo, qhi;\n\t"
        "mov.b64 {plo, phi}, %1;\n\t"
        "mov.b64 {qlo, qhi}, %2;\n\t"
        "mov.b64 %0, {phi, qlo};\n\t"
        "}"
        : "=l"(r) : "l"(p), "l"(q));
    return r;
}

__global__ __launch_bounds__(NTHREADS, 2)
void costvol_kernel(const float* __restrict__ c1,
                    const float* __restrict__ warped,
                    const float* __restrict__ alpha,
                    float* __restrict__ out) {
    extern __shared__ float smem[];

    const int q  = threadIdx.x;   // x-oct 0..3 (x = 8q..8q+7)
    const int ly = threadIdx.y;   // tile row 0..7
    const int dz = threadIdx.z;   // dy 0..8 (one warp per dz)
    const int tid = q + 4 * (ly + 8 * dz);

    const int x0 = blockIdx.x * TW;
    const int y0 = blockIdx.y * TH;
    const int b  = blockIdx.z;

    const float* __restrict__ c1b = c1 + (size_t)b * C_ * HW;
    const float* __restrict__ wb  = warped + (size_t)b * C_ * HW;

    // ---- staging slots as advancing global pointers ----
    const float* gp[SLOTS];
    uint32_t soff[SLOTS];
#pragma unroll
    for (int s = 0; s < SLOTS; s++) {
        gp[s] = nullptr; soff[s] = 0;
        int i = tid + NTHREADS * s;
        if (i < UW) {
            int cc = i / (HALO_H * 10);
            int rem = i % (HALO_H * 10);
            int hy = rem / 10;
            int seg = rem % 10;
            int gy = y0 + hy - SR;
            int gx = x0 - SR + seg * 4;
            soff[s] = (uint32_t)(cc * (HALO_H * SWROW) + hy * SWROW + seg * 4) * 4u;
            if (gy >= 0 && gy < H_ && gx >= 0 && gx + 4 <= W_)
                gp[s] = wb + cc * HW + gy * W_ + gx;
        } else if (i < UTOT) {
            int j = i - UW;
            int cc = j / (TH * 8);
            int rem = j % (TH * 8);
            int yy = rem / 8;
            int seg = rem % 8;
            soff[s] = (uint32_t)(SW_ELEMS + cc * (TH * SAROW) + yy * SAROW + seg * 4) * 4u;
            gp[s] = c1b + cc * HW + (y0 + yy) * W_ + (x0 + seg * 4);
        }
    }

    // ---- zero warped regions once in all stages (OOB halo padding persists) ----
    for (int st = 0; st < NSTAGES; st++)
        for (int i = tid; i < SW_ELEMS; i += NTHREADS)
            smem[st * STAGE + i] = 0.f;
    __syncthreads();

    const uint32_t smem_u32 = (uint32_t)__cvta_generic_to_shared(smem);

    auto issue_stage = [&](int kmod) {
        const uint32_t sbase = smem_u32 + (uint32_t)(kmod * STAGE) * 4u;
#pragma unroll
        for (int s = 0; s < SLOTS; s++) {
            if (gp[s]) {
                uint32_t sa = sbase + soff[s];
                asm volatile("cp.async.cg.shared.global [%0], [%1], 16;"
                             :: "r"(sa), "l"(gp[s]) : "memory");
                gp[s] += CC * HW;
            }
        }
        asm volatile("cp.async.commit_group;" ::: "memory");
    };

    issue_stage(0);
    issue_stage(1);
    issue_stage(2);

    // accumulators (8-wide):
    //  even dx=2d: accE[d][m], m: x-pairs (0,1)(2,3)(4,5)(6,7)
    //  odd  dx=2o+1: x0 scalar, pairs (1,2)(3,4)(5,6) in accO[o][m], x7 scalar
    ull accE[5][4], accO[4][3];
    float acc0[4], acc7[4];
#pragma unroll
    for (int d = 0; d < 5; d++)
#pragma unroll
        for (int m = 0; m < 4; m++) accE[d][m] = 0ull;
#pragma unroll
    for (int o = 0; o < 4; o++) {
#pragma unroll
        for (int m = 0; m < 3; m++) accO[o][m] = 0ull;
        acc0[o] = 0.f; acc7[o] = 0.f;
    }

    // fixed per-thread smem offsets
    const float* a_base = smem + SW_ELEMS + ly * SAROW + 8 * q;
    const float* w_base = smem + (ly + dz) * SWROW + 8 * q;

    int kmod = 0;          // k % 3, maintained by rotation
    for (int k = 0; k < NCH; k++) {
        if (k == 0) {
            asm volatile("cp.async.wait_group 2;" ::: "memory");
        } else if (k + 1 < NCH) {
            asm volatile("cp.async.wait_group 1;" ::: "memory");
        } else {
            asm volatile("cp.async.wait_group 0;" ::: "memory");
        }
        __syncthreads();   // stage k visible; all threads done with chunk k-1

        // buffer (k-1)%3 == (k+2)%3 now free -> refill
        if (k >= 1 && k + 2 < NCH) {
            int knext = kmod - 1; if (knext < 0) knext += NSTAGES;
            issue_stage(knext);
        }

        const float* as = a_base + kmod * STAGE;
        const float* ws = w_base + kmod * STAGE;

#pragma unroll
        for (int cc = 0; cc < CC; cc++) {
            // a: 8 floats -> 4 even pairs straight from 2x LDS.128
            ulonglong2 ua0 = *reinterpret_cast<const ulonglong2*>(as + cc * (TH * SAROW));
            ulonglong2 ua1 = *reinterpret_cast<const ulonglong2*>(as + cc * (TH * SAROW) + 4);
            ull Ae[4] = {ua0.x, ua0.y, ua1.x, ua1.y};
            float a0, a1x, a6x, a7;
            upk(Ae[0], a0, a1x);
            upk(Ae[3], a6x, a7);
            // odd-shifted a pairs (a1,a2)(a3,a4)(a5,a6)
            ull Ao[3] = {mkodd(Ae[0], Ae[1]), mkodd(Ae[1], Ae[2]), mkodd(Ae[2], Ae[3])};

            // w: 16 floats -> 8 even pairs straight from 4x LDS.128
            const float* wrow = ws + cc * (HALO_H * SWROW);
            ulonglong2 u0 = *reinterpret_cast<const ulonglong2*>(wrow);
            ulonglong2 u1 = *reinterpret_cast<const ulonglong2*>(wrow + 4);
            ulonglong2 u2 = *reinterpret_cast<const ulonglong2*>(wrow + 8);
            ulonglong2 u3 = *reinterpret_cast<const ulonglong2*>(wrow + 12);
            ull P[8] = {u0.x, u0.y, u1.x, u1.y, u2.x, u2.y, u3.x, u3.y};

            // even dx = 2d: (a2m,a2m+1)*(w2d+2m, w2d+2m+1)
#pragma unroll
            for (int d = 0; d < 5; d++)
#pragma unroll
                for (int m = 0; m < 4; m++)
                    fma2(accE[d][m], Ae[m], P[d + m]);

            // odd dx = 2o+1
#pragma unroll
            for (int o = 0; o < 4; o++) {
                float wlo, whi;
                upk(P[o], wlo, whi);              // whi = w[2o+1] = w[dx]
                acc0[o] = fmaf(a0, whi, acc0[o]); // x0
#pragma unroll
                for (int m = 0; m < 3; m++)
                    fma2(accO[o][m], Ao[m], P[o + 1 + m]);
                upk(P[o + 4], wlo, whi);          // wlo = w[2o+8] = w[dx+7]
                acc7[o] = fmaf(a7, wlo, acc7[o]); // x7
            }
        }

        kmod++; if (kmod == NSTAGES) kmod = 0;
    }

    // ---- epilogue: mean + leaky, 2x float4 stores per dx ----
    const float al = __ldg(alpha);
    const float inv = 1.0f / (float)C_;
    const int gy = y0 + ly;
    const int gxbase = x0 + q * 8;

    auto emit = [&](int dx, const float* v8) {
        int o = dz * MO + dx;
        float* dst = out + ((size_t)(b * 81 + o) * H_ + gy) * W_ + gxbase;
        float4 v;
        float t;
        t = v8[0] * inv; v.x = (t >= 0.f) ? t : al * t;
        t = v8[1] * inv; v.y = (t >= 0.f) ? t : al * t;
        t = v8[2] * inv; v.z = (t >= 0.f) ? t : al * t;
        t = v8[3] * inv; v.w = (t >= 0.f) ? t : al * t;
        *reinterpret_cast<float4*>(dst) = v;
        t = v8[4] * inv; v.x = (t >= 0.f) ? t : al * t;
        t = v8[5] * inv; v.y = (t >= 0.f) ? t : al * t;
        t = v8[6] * inv; v.z = (t >= 0.f) ? t : al * t;
        t = v8[7] * inv; v.w = (t >= 0.f) ? t : al * t;
        *reinterpret_cast<float4*>(dst + 4) = v;
    };

#pragma unroll
    for (int d = 0; d < 5; d++) {
        float v8[8];
        upk(accE[d][0], v8[0], v8[1]);
        upk(accE[d][1], v8[2], v8[3]);
        upk(accE[d][2], v8[4], v8[5]);
        upk(accE[d][3], v8[6], v8[7]);
        emit(2 * d, v8);
    }
#pragma unroll
    for (int o = 0; o < 4; o++) {
        float v8[8];
        v8[0] = acc0[o];
        upk(accO[o][0], v8[1], v8[2]);
        upk(accO[o][1], v8[3], v8[4]);
        upk(accO[o][2], v8[5], v8[6]);
        v8[7] = acc7[o];
        emit(2 * o + 1, v8);
    }
}

extern "C" void kernel_launch(void* const* d_in, const int* in_sizes, int n_in,
                              void* d_out, int out_size) {
    const float* c1     = (const float*)d_in[0];
    const float* warped = (const float*)d_in[1];
    const float* alpha  = (const float*)d_in[2];
    float* out = (float*)d_out;

    cudaFuncSetAttribute(costvol_kernel,
                         cudaFuncAttributeMaxDynamicSharedMemorySize, SMEM_BYTES);

    dim3 block(4, 8, 9);              // 288 threads, 2 CTAs/SM
    dim3 grid(W_ / TW, H_ / TH, B_);  // (5, 16, 8) = 640 blocks
    costvol_kernel<<<grid, block, SMEM_BYTES>>>(c1, warped, alpha, out);
}